// round 5
// baseline (speedup 1.0000x reference)
#include <cuda_runtime.h>
#include <cuda_fp16.h>
#include <math.h>

// ---------------- problem dims ----------------
#define BB    64
#define NN    1024
#define H16   256
#define H64   1024
#define H128  2048
#define NGATE 8192

#define NCTA_MAX 148
#define USM 13                                   // units whose weights live in SMEM
// dynamic SMEM layout for lstm kernel
#define WSM_BYTES (USM * 4 * 2048 * 2)           // 212992
#define OFF_H32   (WSM_BYTES)                    // fp32 h copy   (8192 B)
#define OFF_H16   (OFF_H32 + H128 * 4)           // fp16 h copy   (4096 B)
#define OFF_G     (OFF_H16 + H128 * 2)           // gate preacts  (256 B)
#define OFF_C     (OFF_G + 64 * 4)               // cell state    (64 B)
#define LSTM_SMEM (OFF_C + 64)                   // 225664 B

// ---------------- device scratch ----------------
__device__ __align__(16) float g_x [BB * NN];
__device__ __align__(16) float g_af[BB * H16];
__device__ __align__(16) float g_ai[BB * H64];
__device__ __align__(16) float g_z [BB * H128];
__device__ __align__(16) float g_gi[BB * NGATE];
__device__ __align__(16) float g_part[1 << 21];      // split-K partials (8MB)
__device__ __align__(16) float g_h [2][H128];
__device__ unsigned g_slot [NCTA_MAX * 8];           // lstm barrier slots
__device__ unsigned g_slot2[NCTA_MAX * 8];           // mlp barrier slots

__global__ void reset_kernel() {
    for (int i = threadIdx.x; i < NCTA_MAX * 8; i += blockDim.x) {
        g_slot[i] = 0u; g_slot2[i] = 0u;
    }
}

// ---------------- spread-slot grid barrier ----------------
__device__ __forceinline__ void grid_bar(volatile unsigned* slots, int ncta, unsigned& gen)
{
    __syncthreads();
    unsigned tgt = ++gen;
    if (threadIdx.x == 0) { __threadfence(); slots[blockIdx.x * 8] = tgt; }
    if ((int)threadIdx.x < ncta) { while (slots[threadIdx.x * 8] < tgt) {} }
    __syncthreads();
}

// ---------------- GCN: one block per sample ----------------
__global__ __launch_bounds__(1024) void gcn_kernel(
    const float* __restrict__ inp,
    const float* __restrict__ gc1w, const float* __restrict__ gc1b,
    const float* __restrict__ gc2w, const float* __restrict__ gc2b)
{
    __shared__ float xs[NN];
    __shared__ float s2[NN];
    const int s = blockIdx.x;
    const int i = threadIdx.x;
    xs[i] = inp[s * NN + i];
    __syncthreads();
    const float xi = xs[i];

    float d0 = INFINITY, d1 = INFINITY, d2 = INFINITY, d3 = INFINITY;
    int i0 = 0, i1 = 0, i2 = 0, i3 = 0;
#pragma unroll 4
    for (int j = 0; j < NN; ++j) {
        float dj = fabsf(xi - xs[j]);
        if (j != i && dj < d3) {
            if (dj < d2) {
                d3 = d2; i3 = i2;
                if (dj < d1) {
                    d2 = d1; i2 = i1;
                    if (dj < d0) { d1 = d0; i1 = i0; d0 = dj; i0 = j; }
                    else         { d1 = dj; i1 = j; }
                } else { d2 = dj; i2 = j; }
            } else { d3 = dj; i3 = j; }
        }
    }

    float S = xs[i0] + xs[i1] + xs[i2] + xs[i3];
    float v = 0.f;
#pragma unroll
    for (int c = 0; c < 4; ++c) {
        float hc = fmaxf(gc1w[c] * S + gc1b[c], 0.f);
        v += hc * gc2w[c];
    }
    s2[i] = v;
    __syncthreads();
    g_x[s * NN + i] = s2[i0] + s2[i1] + s2[i2] + s2[i3] + gc2b[0];
}

// ---------------- fused MLP: persistent kernel, internal barriers ----------------
// Tile worker: 64x64 output tile, 256 threads, 4x4 microtile, split-K chunks.
template <int R, int J, int KC>
__device__ __forceinline__ void gemm_tiles(
    const float* __restrict__ A, const float* __restrict__ W, float* __restrict__ part,
    int bid, int ncta, float (&As)[64][33], float (&Ws)[64][33])
{
    const int JC = J / KC;
    const int RT = R / 64;
    const int tid = threadIdx.x;
    const int tq = tid & 15;
    const int rq = tid >> 4;

    for (int tile = bid; tile < RT * KC; tile += ncta) {
        const int rt = tile % RT, kc = tile / RT;
        const int br0 = rt * 64;

        float acc[4][4];
#pragma unroll
        for (int a = 0; a < 4; ++a)
#pragma unroll
            for (int b = 0; b < 4; ++b) acc[a][b] = 0.f;

        const int jend = (kc + 1) * JC;
        for (int j0 = kc * JC; j0 < jend; j0 += 32) {
            __syncthreads();
#pragma unroll
            for (int idx = tid; idx < 64 * 32; idx += 256) {
                int row = idx >> 5, col = idx & 31;
                As[row][col] = A[row * J + j0 + col];
                Ws[row][col] = W[(size_t)(br0 + row) * J + j0 + col];
            }
            __syncthreads();
#pragma unroll
            for (int kk = 0; kk < 32; ++kk) {
                float av[4], wv[4];
#pragma unroll
                for (int a = 0; a < 4; ++a) av[a] = As[tq + 16 * a][kk];
#pragma unroll
                for (int b = 0; b < 4; ++b) wv[b] = Ws[rq + 16 * b][kk];
#pragma unroll
                for (int a = 0; a < 4; ++a)
#pragma unroll
                    for (int b = 0; b < 4; ++b) acc[a][b] += av[a] * wv[b];
            }
        }
#pragma unroll
        for (int a = 0; a < 4; ++a)
#pragma unroll
            for (int b = 0; b < 4; ++b)
                part[(size_t)kc * 64 * R + (tq + 16 * a) * R + br0 + rq + 16 * b] = acc[a][b];
    }
}

template <int R, int KC, bool RELU, bool HASB2>
__device__ __forceinline__ void reduce_layer(
    const float* __restrict__ part, const float* __restrict__ b1,
    const float* __restrict__ b2, float* __restrict__ C, int bid, int ncta)
{
    for (int i = bid * 256 + threadIdx.x; i < 64 * R; i += ncta * 256) {
        int r = i % R;
        float s = 0.f;
#pragma unroll
        for (int kc = 0; kc < KC; ++kc) s += part[(size_t)kc * 64 * R + i];
        s += b1[r];
        if (HASB2) s += b2[r];
        if (RELU) s = fmaxf(s, 0.f);
        C[i] = s;
    }
}

__global__ __launch_bounds__(256, 1) void mlp_kernel(
    const float* __restrict__ flw, const float* __restrict__ flb,
    const float* __restrict__ ilw, const float* __restrict__ ilb,
    const float* __restrict__ olw, const float* __restrict__ olb,
    const float* __restrict__ wih, const float* __restrict__ bih,
    const float* __restrict__ bhh, int ncta)
{
    __shared__ float As[64][33];
    __shared__ float Ws[64][33];
    const int bid = blockIdx.x;
    volatile unsigned* slots = (volatile unsigned*)g_slot2;
    unsigned gen = 0;

    // fl: [64,256] = x @ fl_w.T ; relu
    gemm_tiles<H16, NN, 32>(g_x, flw, g_part, bid, ncta, As, Ws);
    grid_bar(slots, ncta, gen);
    reduce_layer<H16, 32, true, false>(g_part, flb, nullptr, g_af, bid, ncta);
    grid_bar(slots, ncta, gen);
    // il: [64,1024] = af @ il_w.T ; relu
    gemm_tiles<H64, H16, 8>(g_af, ilw, g_part, bid, ncta, As, Ws);
    grid_bar(slots, ncta, gen);
    reduce_layer<H64, 8, true, false>(g_part, ilb, nullptr, g_ai, bid, ncta);
    grid_bar(slots, ncta, gen);
    // ol: [64,2048] = ai @ ol_w.T ; relu -> z
    gemm_tiles<H128, H64, 4>(g_ai, olw, g_part, bid, ncta, As, Ws);
    grid_bar(slots, ncta, gen);
    reduce_layer<H128, 4, true, false>(g_part, olb, nullptr, g_z, bid, ncta);
    grid_bar(slots, ncta, gen);
    // gate: [64,8192] = z @ w_ih.T + b_ih + b_hh
    gemm_tiles<NGATE, H128, 4>(g_z, wih, g_part, bid, ncta, As, Ws);
    grid_bar(slots, ncta, gen);
    reduce_layer<NGATE, 4, false, true>(g_part, bih, bhh, g_gi, bid, ncta);
}

__device__ __forceinline__ float sigmoidf_(float x) { return 1.f / (1.f + expf(-x)); }

// ---------------- persistent LSTM: SMEM fp16 weights, HFMA2 inner loop ----------------
__global__ __launch_bounds__(1024, 1) void lstm_kernel(
    const float* __restrict__ w_hh, float* __restrict__ out, int ncta)
{
    extern __shared__ unsigned char sm[];
    __half* w_sm = (__half*)sm;                     // [4*usm][2048]
    float*  h32  = (float*)(sm + OFF_H32);          // [2048] fp32 h
    __half* h16  = (__half*)(sm + OFF_H16);         // [2048] fp16 h
    float*  gsm  = (float*)(sm + OFF_G);            // [64]
    float*  csm  = (float*)(sm + OFF_C);            // [16]

    const int tid  = threadIdx.x;
    const int bid  = blockIdx.x;
    const int warp = tid >> 5, lane = tid & 31;

    const int base = H128 / ncta;
    const int rem  = H128 - base * ncta;
    const int nu   = (bid < rem) ? base + 1 : base;   // units this CTA (13/14)
    const int u0   = bid * base + min(bid, rem);
    const int usm  = (nu < USM) ? nu : USM;
    const bool active = (warp < nu);                  // 4 rows per active warp

    // prologue: convert this CTA's SMEM-resident rows fp32 -> fp16
    {
        const int tot2 = usm * 4 * 1024;              // float2 count
        __half2* dst = (__half2*)w_sm;
        for (int idx = tid; idx < tot2; idx += 1024) {
            int sr = idx >> 10, c2 = idx & 1023;
            int g = sr / usm, ui = sr - g * usm;
            const float2* src = (const float2*)(w_hh + (size_t)(g * H128 + u0 + ui) * H128);
            float2 v = src[c2];
            dst[(size_t)sr * 1024 + c2] = __floats2half2_rn(v.x, v.y);
        }
    }

    // row assignment: warp handles rows lr = 4*warp + rr
    int rowg[4]; bool insm[4];
    const uint4* wrow[4]; const float4* wf[4];
    if (active) {
#pragma unroll
        for (int rr = 0; rr < 4; ++rr) {
            int lr = 4 * warp + rr;
            int g = lr / nu, ui = lr - g * nu;
            rowg[rr] = g * H128 + u0 + ui;
            insm[rr] = (ui < usm);
            wrow[rr] = (const uint4*)(w_sm + (size_t)(g * usm + ui) * H128);
            wf[rr]   = (const float4*)(w_hh + (size_t)rowg[rr] * H128);
        }
    }

    volatile unsigned* slots = (volatile unsigned*)g_slot;

    if (tid < nu) { csm[tid] = 0.f; g_h[0][u0 + tid] = 0.f; }
    __syncthreads();
    if (tid == 0) { __threadfence(); slots[bid * 8] = 1u; }
    if (tid < ncta) { while (slots[tid * 8] < 1u) {} }
    __syncthreads();

    for (int t = 0; t < BB; ++t) {
        // broadcast h into SMEM (fp32 + fp16 copies)
        if (tid < H128 / 4) {
            float4 v = __ldcg(&((const float4*)g_h[t & 1])[tid]);
            ((float4*)h32)[tid] = v;
            ((__half2*)h16)[2 * tid]     = __floats2half2_rn(v.x, v.y);
            ((__half2*)h16)[2 * tid + 1] = __floats2half2_rn(v.z, v.w);
        }
        // prefetch gate-input bias terms (hide L2/DRAM latency behind compute)
        float gi[4] = {0.f, 0.f, 0.f, 0.f};
        if (active && lane == 0) {
#pragma unroll
            for (int rr = 0; rr < 4; ++rr) gi[rr] = g_gi[t * NGATE + rowg[rr]];
        }
        __syncthreads();

        if (active) {
            float acc[4] = {0.f, 0.f, 0.f, 0.f};
            const uint4*  h16u = (const uint4*)h16;
            const float4* h32f = (const float4*)h32;
#pragma unroll
            for (int i = 0; i < 8; ++i) {
                const int o = lane + 32 * i;
                uint4 hh = h16u[o];
                const __half2* hp = (const __half2*)&hh;
#pragma unroll
                for (int rr = 0; rr < 4; ++rr) {
                    if (insm[rr]) {
                        uint4 ww = wrow[rr][o];
                        const __half2* wp = (const __half2*)&ww;
                        __half2 s = __hmul2(wp[0], hp[0]);
                        s = __hfma2(wp[1], hp[1], s);
                        s = __hfma2(wp[2], hp[2], s);
                        s = __hfma2(wp[3], hp[3], s);
                        float2 f = __half22float2(s);
                        acc[rr] += f.x + f.y;
                    } else {
                        float4 wa = __ldg(wf[rr] + 2 * o);
                        float4 wb = __ldg(wf[rr] + 2 * o + 1);
                        float4 ha = h32f[2 * o], hb = h32f[2 * o + 1];
                        acc[rr] += wa.x * ha.x + wa.y * ha.y + wa.z * ha.z + wa.w * ha.w
                                 + wb.x * hb.x + wb.y * hb.y + wb.z * hb.z + wb.w * hb.w;
                    }
                }
            }
#pragma unroll
            for (int rr = 0; rr < 4; ++rr)
#pragma unroll
                for (int o = 16; o > 0; o >>= 1) acc[rr] += __shfl_xor_sync(0xffffffffu, acc[rr], o);
            if (lane == 0) {
#pragma unroll
                for (int rr = 0; rr < 4; ++rr) gsm[4 * warp + rr] = acc[rr] + gi[rr];
            }
        }
        __syncthreads();

        if (tid < nu) {
            float ig = gsm[tid], fg = gsm[nu + tid], gg = gsm[2 * nu + tid], og = gsm[3 * nu + tid];
            float c = sigmoidf_(fg) * csm[tid] + sigmoidf_(ig) * tanhf(gg);
            float h = sigmoidf_(og) * tanhf(c);
            csm[tid] = c;
            g_h[(t + 1) & 1][u0 + tid] = h;
            out[t * H128 + u0 + tid] = h;
        }
        __syncthreads();
        if (tid == 0) { __threadfence(); slots[bid * 8] = (unsigned)(t + 2); }
        if (tid < ncta) { unsigned tgt = (unsigned)(t + 2); while (slots[tid * 8] < tgt) {} }
        __syncthreads();
    }
}

// ---------------- launch ----------------
extern "C" void kernel_launch(void* const* d_in, const int* in_sizes, int n_in,
                              void* d_out, int out_size)
{
    const float* inp  = (const float*)d_in[0];
    const float* gc1w = (const float*)d_in[3];
    const float* gc1b = (const float*)d_in[4];
    const float* gc2w = (const float*)d_in[5];
    const float* gc2b = (const float*)d_in[6];
    const float* flw  = (const float*)d_in[7];
    const float* flb  = (const float*)d_in[8];
    const float* ilw  = (const float*)d_in[9];
    const float* ilb  = (const float*)d_in[10];
    const float* olw  = (const float*)d_in[11];
    const float* olb  = (const float*)d_in[12];
    const float* wih  = (const float*)d_in[13];
    const float* whh  = (const float*)d_in[14];
    const float* bih  = (const float*)d_in[15];
    const float* bhh  = (const float*)d_in[16];
    float* out = (float*)d_out;

    int sms = 0;
    cudaDeviceGetAttribute(&sms, cudaDevAttrMultiProcessorCount, 0);
    int ncta = sms;
    if (ncta > NCTA_MAX) ncta = NCTA_MAX;
    if (ncta < 128) ncta = 128;

    cudaFuncSetAttribute(lstm_kernel, cudaFuncAttributeMaxDynamicSharedMemorySize, LSTM_SMEM);

    reset_kernel<<<1, 256>>>();
    gcn_kernel<<<BB, NN>>>(inp, gc1w, gc1b, gc2w, gc2b);
    mlp_kernel<<<ncta, 256>>>(flw, flb, ilw, ilb, olw, olb, wih, bih, bhh, ncta);
    lstm_kernel<<<ncta, 1024, LSTM_SMEM>>>(whh, out, ncta);
}

// round 6
// speedup vs baseline: 2.2648x; 2.2648x over previous
#include <cuda_runtime.h>
#include <cuda_fp16.h>
#include <math.h>

// ---------------- problem dims ----------------
#define BB    64
#define NN    1024
#define H16   256
#define H64   1024
#define H128  2048
#define NGATE 8192

#define NCTA_MAX 148
#define USM 13                                   // units whose fp16 weights live in SMEM
// dynamic SMEM layout for lstm kernel
#define WSM_BYTES (USM * 4 * 2048 * 2)           // 212992
#define OFF_H32   (WSM_BYTES)                    // fp32 h copy   (8192 B)
#define OFF_H16   (OFF_H32 + H128 * 4)           // fp16 h copy   (4096 B)
#define OFF_G     (OFF_H16 + H128 * 2)           // gate preacts  (256 B)
#define OFF_C     (OFF_G + 64 * 4)               // cell state    (64 B)
#define LSTM_SMEM (OFF_C + 64)                   // 225664 B

// ---------------- device scratch ----------------
__device__ __align__(16) float g_x [BB * NN];
__device__ __align__(16) float g_af[BB * H16];
__device__ __align__(16) float g_ai[BB * H64];
__device__ __align__(16) float g_z [BB * H128];
__device__ __align__(16) float g_gi[BB * NGATE];
__device__ __align__(16) float g_part[1 << 21];      // split-K partials (8MB)
__device__ __align__(16) float g_h [2][H128];
__device__ unsigned g_slot[NCTA_MAX * 8];            // spread barrier slots (32B apart)

__global__ void reset_kernel() {
    for (int i = threadIdx.x; i < NCTA_MAX * 8; i += blockDim.x) g_slot[i] = 0u;
}

// ---------------- GCN: one block per sample ----------------
__global__ __launch_bounds__(1024) void gcn_kernel(
    const float* __restrict__ inp,
    const float* __restrict__ gc1w, const float* __restrict__ gc1b,
    const float* __restrict__ gc2w, const float* __restrict__ gc2b)
{
    __shared__ float xs[NN];
    __shared__ float s2[NN];
    const int s = blockIdx.x;
    const int i = threadIdx.x;
    xs[i] = inp[s * NN + i];
    __syncthreads();
    const float xi = xs[i];

    float d0 = INFINITY, d1 = INFINITY, d2 = INFINITY, d3 = INFINITY;
    int i0 = 0, i1 = 0, i2 = 0, i3 = 0;
#pragma unroll 4
    for (int j = 0; j < NN; ++j) {
        float dj = fabsf(xi - xs[j]);
        if (j != i && dj < d3) {
            if (dj < d2) {
                d3 = d2; i3 = i2;
                if (dj < d1) {
                    d2 = d1; i2 = i1;
                    if (dj < d0) { d1 = d0; i1 = i0; d0 = dj; i0 = j; }
                    else         { d1 = dj; i1 = j; }
                } else { d2 = dj; i2 = j; }
            } else { d3 = dj; i3 = j; }
        }
    }

    float S = xs[i0] + xs[i1] + xs[i2] + xs[i3];
    float v = 0.f;
#pragma unroll
    for (int c = 0; c < 4; ++c) {
        float hc = fmaxf(gc1w[c] * S + gc1b[c], 0.f);
        v += hc * gc2w[c];
    }
    s2[i] = v;
    __syncthreads();
    g_x[s * NN + i] = s2[i0] + s2[i1] + s2[i2] + s2[i3] + gc2b[0];
}

// ---------------- small split-K GEMM (64xR', 128 thr) for fl/il ----------------
template <int R, int J, int KC>
__global__ __launch_bounds__(128) void gemm_sk(
    const float* __restrict__ A, const float* __restrict__ W, float* __restrict__ part)
{
    __shared__ float As[64][33];
    __shared__ float Ws[32][33];
    const int JC  = J / KC;
    const int kc  = blockIdx.y;
    const int br0 = blockIdx.x * 32;
    const int tid = threadIdx.x;
    const int tq  = tid & 15;
    const int rq  = tid >> 4;

    float acc[4][4];
#pragma unroll
    for (int a = 0; a < 4; ++a)
#pragma unroll
        for (int b = 0; b < 4; ++b) acc[a][b] = 0.f;

    const int j_end = (kc + 1) * JC;
    for (int j0 = kc * JC; j0 < j_end; j0 += 32) {
        for (int idx = tid; idx < 64 * 32; idx += 128) {
            int row = idx >> 5, col = idx & 31;
            As[row][col] = A[row * J + j0 + col];
        }
        for (int idx = tid; idx < 32 * 32; idx += 128) {
            int row = idx >> 5, col = idx & 31;
            Ws[row][col] = W[(size_t)(br0 + row) * J + j0 + col];
        }
        __syncthreads();
#pragma unroll
        for (int kk = 0; kk < 32; ++kk) {
            float av[4], wv[4];
#pragma unroll
            for (int a = 0; a < 4; ++a) av[a] = As[tq + 16 * a][kk];
#pragma unroll
            for (int b = 0; b < 4; ++b) wv[b] = Ws[rq + 8 * b][kk];
#pragma unroll
            for (int a = 0; a < 4; ++a)
#pragma unroll
                for (int b = 0; b < 4; ++b) acc[a][b] += av[a] * wv[b];
        }
        __syncthreads();
    }
#pragma unroll
    for (int a = 0; a < 4; ++a)
#pragma unroll
        for (int b = 0; b < 4; ++b)
            part[(size_t)kc * 64 * R + (tq + 16 * a) * R + br0 + rq + 8 * b] = acc[a][b];
}

// ---------------- big split-K GEMM: 64x64 tile, 256 thr, double-buffered ----------------
template <int R, int J, int KC>
__global__ __launch_bounds__(256) void gemm64(
    const float* __restrict__ A, const float* __restrict__ W, float* __restrict__ part)
{
    __shared__ float As[2][64][33];
    __shared__ float Ws[2][64][33];
    const int JC  = J / KC;
    const int kc  = blockIdx.y;
    const int br0 = blockIdx.x * 64;
    const int tid = threadIdx.x;
    const int tq  = tid & 15;
    const int rq  = tid >> 4;

    float acc[4][4];
#pragma unroll
    for (int a = 0; a < 4; ++a)
#pragma unroll
        for (int b = 0; b < 4; ++b) acc[a][b] = 0.f;

    const int jbeg = kc * JC;
    const int nit  = JC / 32;

    auto load = [&](int s, int j0) {
#pragma unroll
        for (int idx = tid; idx < 64 * 32; idx += 256) {
            int row = idx >> 5, col = idx & 31;
            As[s][row][col] = A[row * J + j0 + col];
            Ws[s][row][col] = W[(size_t)(br0 + row) * J + j0 + col];
        }
    };

    load(0, jbeg);
    __syncthreads();
    for (int it = 0; it < nit; ++it) {
        int s = it & 1;
        if (it + 1 < nit) load(s ^ 1, jbeg + (it + 1) * 32);
#pragma unroll
        for (int kk = 0; kk < 32; ++kk) {
            float av[4], wv[4];
#pragma unroll
            for (int a = 0; a < 4; ++a) av[a] = As[s][tq + 16 * a][kk];
#pragma unroll
            for (int b = 0; b < 4; ++b) wv[b] = Ws[s][rq + 16 * b][kk];
#pragma unroll
            for (int a = 0; a < 4; ++a)
#pragma unroll
                for (int b = 0; b < 4; ++b) acc[a][b] += av[a] * wv[b];
        }
        __syncthreads();
    }
#pragma unroll
    for (int a = 0; a < 4; ++a)
#pragma unroll
        for (int b = 0; b < 4; ++b)
            part[(size_t)kc * 64 * R + (tq + 16 * a) * R + br0 + rq + 16 * b] = acc[a][b];
}

// ---------------- reduce partials ----------------
template <int R, int KC, bool RELU, bool HASB2>
__global__ __launch_bounds__(256) void reduce_k(
    const float* __restrict__ part,
    const float* __restrict__ b1, const float* __restrict__ b2,
    float* __restrict__ C)
{
    int i = blockIdx.x * 256 + threadIdx.x;
    if (i >= 64 * R) return;
    int r = i % R;
    float s = 0.f;
#pragma unroll
    for (int kc = 0; kc < KC; ++kc) s += part[(size_t)kc * 64 * R + i];
    s += b1[r];
    if (HASB2) s += b2[r];
    if (RELU) s = fmaxf(s, 0.f);
    C[i] = s;
}

__device__ __forceinline__ float sigmoidf_(float x) { return 1.f / (1.f + expf(-x)); }

// ---------------- persistent LSTM: SMEM fp16 weights, ALL warps active ----------------
// ncta CTAs (SM count), nu = 13/14 units per CTA, nrows = 4*nu <= 64.
// Row mapping lr = warp + 32*k (k<2): every warp owns 1-2 rows; h16 read once per
// i-iteration, reused across the warp's rows. usm=13 units' weights in SMEM fp16;
// the (at most 3) spill units' rows are read fp32 from L2 each step (tiny).
__global__ __launch_bounds__(1024, 1) void lstm_kernel(
    const float* __restrict__ w_hh, float* __restrict__ out, int ncta)
{
    extern __shared__ unsigned char sm[];
    __half* w_sm = (__half*)sm;                     // [4*usm][2048] fp16
    float*  h32  = (float*)(sm + OFF_H32);          // [2048]
    __half* h16  = (__half*)(sm + OFF_H16);         // [2048]
    float*  gsm  = (float*)(sm + OFF_G);            // [64]
    float*  csm  = (float*)(sm + OFF_C);            // [16]

    const int tid  = threadIdx.x;
    const int bid  = blockIdx.x;
    const int warp = tid >> 5, lane = tid & 31;

    const int base = H128 / ncta;
    const int rem  = H128 - base * ncta;
    const int nu   = (bid < rem) ? base + 1 : base;
    const int u0   = bid * base + min(bid, rem);
    const int usm  = (nu < USM) ? nu : USM;
    const int nrows = 4 * nu;

    // prologue: convert this CTA's SMEM-resident rows fp32 -> fp16 (once per launch)
    {
        const int tot2 = usm * 4 * 1024;              // float2 count
        __half2* dst = (__half2*)w_sm;
        for (int idx = tid; idx < tot2; idx += 1024) {
            int sr = idx >> 10, c2 = idx & 1023;      // smem row, col-pair
            int g = sr / usm, ui = sr - g * usm;
            const float2* src = (const float2*)(w_hh + (size_t)(g * H128 + u0 + ui) * H128);
            float2 v = src[c2];
            dst[idx] = __floats2half2_rn(v.x, v.y);
        }
    }

    // per-warp row assignment: lr = warp + 32*k
    int cnt = 0;
    int rowg[2], gsl[2];
    bool insm[2];
    const uint4*  wr16[2];
    const float4* wr32[2];
#pragma unroll
    for (int k = 0; k < 2; ++k) {
        int lr = warp + 32 * k;
        if (lr < nrows) {
            int g = lr / nu, ui = lr - g * nu;
            rowg[cnt] = g * H128 + u0 + ui;
            gsl [cnt] = lr;
            insm[cnt] = (ui < usm);
            wr16[cnt] = (const uint4*)(w_sm + (size_t)(g * usm + ui) * H128);
            wr32[cnt] = (const float4*)(w_hh + (size_t)rowg[cnt] * H128);
            ++cnt;
        }
    }

    volatile unsigned* slots = (volatile unsigned*)g_slot;

    if (tid < nu) { csm[tid] = 0.f; g_h[0][u0 + tid] = 0.f; }
    __syncthreads();
    if (tid == 0) { __threadfence(); slots[bid * 8] = 1u; }
    if (tid < ncta) { while (slots[tid * 8] < 1u) {} }
    __threadfence();
    __syncthreads();

    for (int t = 0; t < BB; ++t) {
        // broadcast h into SMEM (fp32 + fp16)
        if (tid < H128 / 4) {
            float4 v = __ldcg(&((const float4*)g_h[t & 1])[tid]);
            ((float4*)h32)[tid] = v;
            ((__half2*)h16)[2 * tid]     = __floats2half2_rn(v.x, v.y);
            ((__half2*)h16)[2 * tid + 1] = __floats2half2_rn(v.z, v.w);
        }
        // prefetch gate-input terms (precomputed, L2) while h settles
        float gi[2] = {0.f, 0.f};
        if (lane == 0) {
#pragma unroll
            for (int k = 0; k < 2; ++k)
                if (k < cnt) gi[k] = g_gi[t * NGATE + rowg[k]];
        }
        __syncthreads();

        float acc[2] = {0.f, 0.f};
        const uint4*  h16u = (const uint4*)h16;
        const float4* h32f = (const float4*)h32;
#pragma unroll
        for (int i = 0; i < 8; ++i) {
            const int o = lane + 32 * i;
            uint4 hh = h16u[o];                        // 8 halfs, shared across rows
            const __half2* hp = (const __half2*)&hh;
#pragma unroll
            for (int k = 0; k < 2; ++k) {
                if (k >= cnt) break;
                if (insm[k]) {
                    uint4 ww = wr16[k][o];
                    const __half2* wp = (const __half2*)&ww;
                    __half2 s = __hmul2(wp[0], hp[0]);
                    s = __hfma2(wp[1], hp[1], s);
                    s = __hfma2(wp[2], hp[2], s);
                    s = __hfma2(wp[3], hp[3], s);
                    float2 f = __half22float2(s);
                    acc[k] += f.x + f.y;
                } else {
                    float4 wa = __ldg(wr32[k] + 2 * o);
                    float4 wb = __ldg(wr32[k] + 2 * o + 1);
                    float4 ha = h32f[2 * o], hb = h32f[2 * o + 1];
                    acc[k] += wa.x * ha.x + wa.y * ha.y + wa.z * ha.z + wa.w * ha.w
                            + wb.x * hb.x + wb.y * hb.y + wb.z * hb.z + wb.w * hb.w;
                }
            }
        }
#pragma unroll
        for (int k = 0; k < 2; ++k)
#pragma unroll
            for (int o = 16; o > 0; o >>= 1) acc[k] += __shfl_xor_sync(0xffffffffu, acc[k], o);
        if (lane == 0) {
#pragma unroll
            for (int k = 0; k < 2; ++k)
                if (k < cnt) gsm[gsl[k]] = acc[k] + gi[k];
        }
        __syncthreads();

        if (tid < nu) {
            float ig = gsm[tid], fg = gsm[nu + tid], gg = gsm[2 * nu + tid], og = gsm[3 * nu + tid];
            float c = sigmoidf_(fg) * csm[tid] + sigmoidf_(ig) * tanhf(gg);
            float h = sigmoidf_(og) * tanhf(c);
            csm[tid] = c;
            g_h[(t + 1) & 1][u0 + tid] = h;
            out[t * H128 + u0 + tid] = h;
        }
        __syncthreads();
        if (tid == 0) { __threadfence(); slots[bid * 8] = (unsigned)(t + 2); }
        if (tid < ncta) { unsigned tgt = (unsigned)(t + 2); while (slots[tid * 8] < tgt) {} }
        __threadfence();
        __syncthreads();
    }
}

// ---------------- launch ----------------
extern "C" void kernel_launch(void* const* d_in, const int* in_sizes, int n_in,
                              void* d_out, int out_size)
{
    const float* inp  = (const float*)d_in[0];
    const float* gc1w = (const float*)d_in[3];
    const float* gc1b = (const float*)d_in[4];
    const float* gc2w = (const float*)d_in[5];
    const float* gc2b = (const float*)d_in[6];
    const float* flw  = (const float*)d_in[7];
    const float* flb  = (const float*)d_in[8];
    const float* ilw  = (const float*)d_in[9];
    const float* ilb  = (const float*)d_in[10];
    const float* olw  = (const float*)d_in[11];
    const float* olb  = (const float*)d_in[12];
    const float* wih  = (const float*)d_in[13];
    const float* whh  = (const float*)d_in[14];
    const float* bih  = (const float*)d_in[15];
    const float* bhh  = (const float*)d_in[16];
    float* out = (float*)d_out;

    void *px, *paf, *pai, *pz, *pgi, *ppart;
    cudaGetSymbolAddress(&px,    g_x);
    cudaGetSymbolAddress(&paf,   g_af);
    cudaGetSymbolAddress(&pai,   g_ai);
    cudaGetSymbolAddress(&pz,    g_z);
    cudaGetSymbolAddress(&pgi,   g_gi);
    cudaGetSymbolAddress(&ppart, g_part);
    float* part = (float*)ppart;

    int sms = 0;
    cudaDeviceGetAttribute(&sms, cudaDevAttrMultiProcessorCount, 0);
    int ncta = sms;
    if (ncta > NCTA_MAX) ncta = NCTA_MAX;
    if (ncta < 128) ncta = 128;

    cudaFuncSetAttribute(lstm_kernel, cudaFuncAttributeMaxDynamicSharedMemorySize, LSTM_SMEM);

    reset_kernel<<<1, 256>>>();
    gcn_kernel<<<BB, NN>>>(inp, gc1w, gc1b, gc2w, gc2b);

    // fl: [64,256] = x @ fl_w.T ; relu
    gemm_sk<H16, NN, 16><<<dim3(H16 / 32, 16), 128>>>((const float*)px, flw, part);
    reduce_k<H16, 16, true, false><<<(64 * H16 + 255) / 256, 256>>>(part, flb, nullptr, (float*)paf);
    // il: [64,1024] = af @ il_w.T ; relu
    gemm_sk<H64, H16, 4><<<dim3(H64 / 32, 4), 128>>>((const float*)paf, ilw, part);
    reduce_k<H64, 4, true, false><<<(64 * H64 + 255) / 256, 256>>>(part, ilb, nullptr, (float*)pai);
    // ol: [64,2048] = ai @ ol_w.T ; relu -> z
    gemm64<H128, H64, 4><<<dim3(H128 / 64, 4), 256>>>((const float*)pai, olw, part);
    reduce_k<H128, 4, true, false><<<(64 * H128 + 255) / 256, 256>>>(part, olb, nullptr, (float*)pz);
    // gate: [64,8192] = z @ w_ih.T + b_ih + b_hh
    gemm64<NGATE, H128, 4><<<dim3(NGATE / 64, 4), 256>>>((const float*)pz, wih, part);
    reduce_k<NGATE, 4, false, true><<<(64 * NGATE + 255) / 256, 256>>>(part, bih, bhh, (float*)pgi);

    lstm_kernel<<<ncta, 1024, LSTM_SMEM>>>(whh, out, ncta);
}